// round 2
// baseline (speedup 1.0000x reference)
#include <cuda_runtime.h>
#include <math.h>

#define BB 128
#define NN 512
#define FT 64
#define DD 64
#define TOPK 20
#define M_ROWS (BB*NN)          // 65536
#define NEG_SLOPE 0.2f
#define BN_EPS 1e-5f
#define AGG_BLOCKS 4096         // 16 rows per block

// ---- scratch (device globals; no allocation allowed) ----
__device__ float g_norm[NN];
__device__ float g_tsrc[NN];
__device__ float g_tdst[NN];
__device__ int   g_topk[NN*TOPK];
__device__ float g_z[M_ROWS*DD];
__device__ float g_ssrc[M_ROWS];
__device__ float g_sdst[M_ROWS];
__device__ float g_rst[M_ROWS*DD];
__device__ float g_psum[AGG_BLOCKS*DD];
__device__ float g_psq[AGG_BLOCKS*DD];
__device__ float g_mu[DD];
__device__ float g_scale[DD];

// ---- kernel A: per-node norms + emb-part of attention scores ----
__global__ void k_prep(const float* __restrict__ emb, const float* __restrict__ attn_w) {
    int n = threadIdx.x;   // 512 threads
    float s2 = 0.f, ts = 0.f, td = 0.f;
    #pragma unroll 16
    for (int d = 0; d < DD; d++) {
        float v = emb[n*DD + d];
        s2 += v*v;
        ts += v*attn_w[DD + d];      // a_src second half = attn_w[64:128]
        td += v*attn_w[3*DD + d];    // a_dst second half = attn_w[192:256]
    }
    g_norm[n] = sqrtf(s2);
    g_tsrc[n] = ts;
    g_tdst[n] = td;
}

// ---- kernel B: cosine similarity row + iterative top-20 (jax tie-break) ----
__global__ void k_topk(const float* __restrict__ emb) {
    int n = blockIdx.x;
    int tid = threadIdx.x;         // 512 threads, thread = candidate column m
    __shared__ float en[DD];
    __shared__ float cosv[NN];
    __shared__ float rv[NN];
    __shared__ int   ri[NN];

    if (tid < DD) en[tid] = emb[n*DD + tid];
    __syncthreads();

    float dot = 0.f;
    #pragma unroll 16
    for (int d = 0; d < DD; d++) dot += en[d] * emb[tid*DD + d];
    cosv[tid] = dot / (g_norm[n] * g_norm[tid]);
    __syncthreads();

    for (int k = 0; k < TOPK; k++) {
        rv[tid] = cosv[tid]; ri[tid] = tid;
        __syncthreads();
        for (int s = NN/2; s > 0; s >>= 1) {
            if (tid < s) {
                float v2 = rv[tid+s]; int i2 = ri[tid+s];
                if (v2 > rv[tid] || (v2 == rv[tid] && i2 < ri[tid])) { rv[tid]=v2; ri[tid]=i2; }
            }
            __syncthreads();
        }
        if (tid == 0) { g_topk[n*TOPK + k] = ri[0]; cosv[ri[0]] = -INFINITY; }
        __syncthreads();
    }
}

// ---- kernel C: z = data @ fc_w^T + fc_b  (M=65536, K=64, N=64) ----
__global__ void k_gemm(const float* __restrict__ data,
                       const float* __restrict__ fc_w,
                       const float* __restrict__ fc_b) {
    __shared__ float sw[64][65];   // fc_w[d][f]
    __shared__ float sa[64][65];   // data rows
    int tid = threadIdx.x;         // 256 threads
    int rowbase = blockIdx.x * 64;

    for (int i = tid; i < 4096; i += 256) sw[i>>6][i&63] = fc_w[i];
    for (int i = tid; i < 4096; i += 256) {
        int r = i>>6, f = i&63;
        sa[r][f] = data[(rowbase + r)*64 + f];
    }
    __syncthreads();

    int r0 = (tid >> 4) * 4, c0 = (tid & 15) * 4;
    float acc[4][4] = {};
    #pragma unroll
    for (int f = 0; f < 64; f++) {
        float av[4], wv[4];
        #pragma unroll
        for (int i = 0; i < 4; i++) av[i] = sa[r0+i][f];
        #pragma unroll
        for (int j = 0; j < 4; j++) wv[j] = sw[c0+j][f];
        #pragma unroll
        for (int i = 0; i < 4; i++)
            #pragma unroll
            for (int j = 0; j < 4; j++)
                acc[i][j] = fmaf(av[i], wv[j], acc[i][j]);
    }
    #pragma unroll
    for (int i = 0; i < 4; i++) {
        float4 o;
        o.x = acc[i][0] + fc_b[c0+0];
        o.y = acc[i][1] + fc_b[c0+1];
        o.z = acc[i][2] + fc_b[c0+2];
        o.w = acc[i][3] + fc_b[c0+3];
        *reinterpret_cast<float4*>(&g_z[(rowbase + r0 + i)*64 + c0]) = o;
    }
}

// ---- kernel D: s_src/s_dst per (b,n)  (warp-per-row dot) ----
__global__ void k_score(const float* __restrict__ attn_w) {
    int w = threadIdx.x >> 5, lane = threadIdx.x & 31;
    int m = blockIdx.x * 8 + w;            // 8192 blocks * 8 warps
    float z0 = g_z[m*64 + lane];
    float z1 = g_z[m*64 + 32 + lane];
    float ds = z0*attn_w[lane]       + z1*attn_w[32 + lane];
    float dd = z0*attn_w[128 + lane] + z1*attn_w[160 + lane];
    #pragma unroll
    for (int o = 16; o > 0; o >>= 1) {
        ds += __shfl_down_sync(0xFFFFFFFFu, ds, o);
        dd += __shfl_down_sync(0xFFFFFFFFu, dd, o);
    }
    if (lane == 0) {
        int n = m & (NN-1);
        g_ssrc[m] = ds + g_tsrc[n];
        g_sdst[m] = dd + g_tdst[n];
    }
}

// ---- kernel E: edge softmax + neighbor aggregate + rst + BN partials ----
__global__ void k_aggr(const float* __restrict__ emb, const float* __restrict__ attn_b) {
    __shared__ float al[16][TOPK];
    __shared__ int   sr[16][TOPK];
    __shared__ float shs[256], shq[256];
    int tid = threadIdx.x;                 // 256 threads, 16 rows/block
    int base = blockIdx.x * 16;

    if (tid < 16) {
        int row = base + tid;
        int b = row >> 9, n = row & (NN-1);
        float sd = g_sdst[row];
        float ab = attn_b[0];
        float e[TOPK];
        float mx = -INFINITY;
        #pragma unroll
        for (int t = 0; t < TOPK; t++) {
            int i = n + t*NN;
            int s = g_topk[(i/TOPK)*TOPK + (i % TOPK)];   // reference's edge wiring
            sr[tid][t] = s;
            float x = g_ssrc[b*NN + s] + sd + ab;
            x = x > 0.f ? x : NEG_SLOPE * x;              // leaky relu
            e[t] = x;
            mx = fmaxf(mx, x);
        }
        float den = 0.f;
        #pragma unroll
        for (int t = 0; t < TOPK; t++) { float p = expf(e[t]-mx); e[t] = p; den += p; }
        float inv = 1.0f / den;
        #pragma unroll
        for (int t = 0; t < TOPK; t++) al[tid][t] = e[t]*inv;
    }
    __syncthreads();

    int d = tid & 63, rg = tid >> 6;       // 4 row-groups
    float ps = 0.f, pq = 0.f;
    #pragma unroll
    for (int rr = 0; rr < 4; rr++) {
        int g = rg + rr*4;
        int row = base + g;
        int b = row >> 9, n = row & (NN-1);
        float h = 0.f;
        const float* zb = &g_z[(size_t)b * NN * 64];
        #pragma unroll
        for (int t = 0; t < TOPK; t++)
            h = fmaf(al[g][t], zb[sr[g][t]*64 + d], h);
        float rv = h * emb[n*64 + d];
        g_rst[row*64 + d] = rv;
        ps += rv; pq += rv*rv;
    }
    shs[tid] = ps; shq[tid] = pq;
    __syncthreads();
    if (tid < 64) {
        float S = shs[tid] + shs[tid+64] + shs[tid+128] + shs[tid+192];
        float Q = shq[tid] + shq[tid+64] + shq[tid+128] + shq[tid+192];
        g_psum[blockIdx.x*64 + tid] = S;
        g_psq [blockIdx.x*64 + tid] = Q;
    }
}

// ---- kernel F: BN statistics (deterministic fixed-order reduce) ----
__global__ void k_stats(const float* __restrict__ bn_gamma) {
    int d = blockIdx.x;                    // 64 blocks
    int tid = threadIdx.x;                 // 256 threads
    __shared__ float shs[256], shq[256];
    float s = 0.f, q = 0.f;
    for (int j = tid; j < AGG_BLOCKS; j += 256) {
        s += g_psum[j*64 + d];
        q += g_psq [j*64 + d];
    }
    shs[tid] = s; shq[tid] = q;
    __syncthreads();
    for (int st = 128; st > 0; st >>= 1) {
        if (tid < st) { shs[tid] += shs[tid+st]; shq[tid] += shq[tid+st]; }
        __syncthreads();
    }
    if (tid == 0) {
        float mu  = shs[0] / (float)M_ROWS;
        float var = shq[0] / (float)M_ROWS - mu*mu;   // biased, matches jnp.var
        g_mu[d]    = mu;
        g_scale[d] = bn_gamma[d] / sqrtf(var + BN_EPS);
    }
}

// ---- kernel G: normalize + relu + output dot ----
__global__ void k_out(const float* __restrict__ bn_beta,
                      const float* __restrict__ out_w,
                      const float* __restrict__ out_b,
                      float* __restrict__ out) {
    int w = threadIdx.x >> 5, lane = threadIdx.x & 31;
    int m = blockIdx.x * 8 + w;            // 8192 blocks * 8 warps
    float a = 0.f;
    #pragma unroll
    for (int dd = lane; dd < 64; dd += 32) {
        float v = (g_rst[m*64 + dd] - g_mu[dd]) * g_scale[dd] + bn_beta[dd];
        v = v > 0.f ? v : 0.f;
        a = fmaf(v, out_w[dd], a);
    }
    #pragma unroll
    for (int o = 16; o > 0; o >>= 1) a += __shfl_down_sync(0xFFFFFFFFu, a, o);
    if (lane == 0) out[m] = a + out_b[0];
}

extern "C" void kernel_launch(void* const* d_in, const int* in_sizes, int n_in,
                              void* d_out, int out_size) {
    const float* data     = (const float*)d_in[0];
    const float* emb      = (const float*)d_in[1];
    const float* fc_w     = (const float*)d_in[2];
    const float* fc_b     = (const float*)d_in[3];
    const float* attn_w   = (const float*)d_in[4];
    const float* attn_b   = (const float*)d_in[5];
    const float* bn_gamma = (const float*)d_in[6];
    const float* bn_beta  = (const float*)d_in[7];
    const float* out_w    = (const float*)d_in[8];
    const float* out_b    = (const float*)d_in[9];
    float* out = (float*)d_out;

    k_prep <<<1, 512>>>(emb, attn_w);
    k_topk <<<NN, NN>>>(emb);
    k_gemm <<<M_ROWS/64, 256>>>(data, fc_w, fc_b);
    k_score<<<M_ROWS/8, 256>>>(attn_w);
    k_aggr <<<AGG_BLOCKS, 256>>>(emb, attn_b);
    k_stats<<<DD, 256>>>(bn_gamma);
    k_out  <<<M_ROWS/8, 256>>>(bn_beta, out_w, out_b, out);
}

// round 3
// speedup vs baseline: 1.2126x; 1.2126x over previous
#include <cuda_runtime.h>
#include <math.h>

#define BB 128
#define NN 512
#define FT 64
#define DD 64
#define TOPK 20
#define M_ROWS (BB*NN)          // 65536
#define NEG_SLOPE 0.2f
#define BN_EPS 1e-5f

// ---- scratch (device globals; no allocation allowed) ----
__device__ float g_tsrc[NN];
__device__ float g_tdst[NN];
__device__ int   g_topk[NN*TOPK];
__device__ float g_z[M_ROWS*DD];
__device__ float g_ssrc[M_ROWS];
__device__ float g_sdst[M_ROWS];
__device__ float g_rst[M_ROWS*DD];
__device__ float g_psum[BB*DD];
__device__ float g_psq[BB*DD];
__device__ float g_mu[DD];
__device__ float g_scale[DD];

// ============================================================
// kernel 1: cos-sim row + top-20 (warp-register selection).
// Also: block 0 computes the emb-half of the attention scores.
// ============================================================
__global__ void k_topk(const float* __restrict__ emb, const float* __restrict__ attn_w) {
    int n = blockIdx.x;
    int tid = threadIdx.x;          // 512 threads; thread = candidate m
    __shared__ float en[DD];
    __shared__ float normv[NN];
    __shared__ float cosv[NN];

    if (tid < DD) en[tid] = emb[n*DD + tid];
    __syncthreads();

    // dot + own norm, same accumulation order as reference path (bit-stable)
    float dot = 0.f, s2 = 0.f;
    #pragma unroll 16
    for (int d = 0; d < DD; d++) {
        float v = emb[tid*DD + d];
        dot += en[d] * v;
        s2  += v * v;
    }
    normv[tid] = sqrtf(s2);
    __syncthreads();
    cosv[tid] = dot / (normv[n] * normv[tid]);

    // block 0 additionally computes tsrc/tdst (emb part of scores)
    if (blockIdx.x == 0) {
        float ts = 0.f, td = 0.f;
        #pragma unroll 16
        for (int d = 0; d < DD; d++) {
            float v = emb[tid*DD + d];
            ts += v * attn_w[DD + d];
            td += v * attn_w[3*DD + d];
        }
        g_tsrc[tid] = ts;
        g_tdst[tid] = td;
    }
    __syncthreads();

    if (tid >= 32) return;
    int lane = tid;

    // lane holds slots j: index = j*32 + lane
    float sl[16];
    #pragma unroll
    for (int j = 0; j < 16; j++) sl[j] = cosv[j*32 + lane];

    for (int k = 0; k < TOPK; k++) {
        // local argmax (ascending j => strict > keeps lowest index per lane)
        float bv = sl[0]; int bi = lane;
        #pragma unroll
        for (int j = 1; j < 16; j++) {
            int idx = j*32 + lane;
            if (sl[j] > bv) { bv = sl[j]; bi = idx; }
        }
        // warp all-reduce with (value desc, index asc) tie-break
        #pragma unroll
        for (int o = 16; o > 0; o >>= 1) {
            float ov = __shfl_xor_sync(0xFFFFFFFFu, bv, o);
            int   oi = __shfl_xor_sync(0xFFFFFFFFu, bi, o);
            if (ov > bv || (ov == bv && oi < bi)) { bv = ov; bi = oi; }
        }
        if (lane == 0) g_topk[n*TOPK + k] = bi;
        if ((bi & 31) == lane) {
            int j = bi >> 5;
            #pragma unroll
            for (int jj = 0; jj < 16; jj++) if (jj == j) sl[jj] = -INFINITY;
        }
    }
}

// ============================================================
// kernel 2: z = data @ fc_w^T + fc_b, fused with score dots.
// Transposed smem tiles -> LDS.128 broadcast loads.
// ============================================================
__global__ void k_gemm(const float* __restrict__ data,
                       const float* __restrict__ fc_w,
                       const float* __restrict__ fc_b,
                       const float* __restrict__ attn_w) {
    __shared__ float sw_t[64][68];   // sw_t[f][d] = fc_w[d][f]
    __shared__ float sa_t[64][68];   // sa_t[f][r] = data[row][f]
    int tid = threadIdx.x;           // 256 threads
    int rowbase = blockIdx.x * 64;

    for (int i = tid; i < 4096; i += 256) sw_t[i & 63][i >> 6] = fc_w[i];
    for (int i = tid; i < 4096; i += 256) sa_t[i & 63][i >> 6] = data[rowbase*64 + i];
    __syncthreads();

    int r0 = (tid >> 4) * 4, c0 = (tid & 15) * 4;
    float acc[4][4] = {};
    #pragma unroll
    for (int f = 0; f < 64; f++) {
        float4 av = *reinterpret_cast<const float4*>(&sa_t[f][r0]);
        float4 wv = *reinterpret_cast<const float4*>(&sw_t[f][c0]);
        float a4[4] = {av.x, av.y, av.z, av.w};
        float w4[4] = {wv.x, wv.y, wv.z, wv.w};
        #pragma unroll
        for (int i = 0; i < 4; i++)
            #pragma unroll
            for (int j = 0; j < 4; j++)
                acc[i][j] = fmaf(a4[i], w4[j], acc[i][j]);
    }

    float4 bb = *reinterpret_cast<const float4*>(&fc_b[c0]);
    float b4[4] = {bb.x, bb.y, bb.z, bb.w};
    float4 as = *reinterpret_cast<const float4*>(&attn_w[c0]);
    float4 ad = *reinterpret_cast<const float4*>(&attn_w[128 + c0]);
    float s4[4] = {as.x, as.y, as.z, as.w};
    float d4[4] = {ad.x, ad.y, ad.z, ad.w};

    float ds[4], dd[4];
    #pragma unroll
    for (int i = 0; i < 4; i++) {
        float4 o;
        float z0 = acc[i][0] + b4[0];
        float z1 = acc[i][1] + b4[1];
        float z2 = acc[i][2] + b4[2];
        float z3 = acc[i][3] + b4[3];
        o.x = z0; o.y = z1; o.z = z2; o.w = z3;
        *reinterpret_cast<float4*>(&g_z[(rowbase + r0 + i)*64 + c0]) = o;
        ds[i] = z0*s4[0] + z1*s4[1] + z2*s4[2] + z3*s4[3];
        dd[i] = z0*d4[0] + z1*d4[1] + z2*d4[2] + z3*d4[3];
    }
    // reduce over the 16 threads (same rows) within the warp half
    #pragma unroll
    for (int o = 8; o > 0; o >>= 1) {
        #pragma unroll
        for (int i = 0; i < 4; i++) {
            ds[i] += __shfl_down_sync(0xFFFFFFFFu, ds[i], o, 16);
            dd[i] += __shfl_down_sync(0xFFFFFFFFu, dd[i], o, 16);
        }
    }
    if ((tid & 15) == 0) {
        #pragma unroll
        for (int i = 0; i < 4; i++) {
            int row = rowbase + r0 + i;
            int n = row & (NN-1);
            g_ssrc[row] = ds[i] + g_tsrc[n];
            g_sdst[row] = dd[i] + g_tdst[n];
        }
    }
}

// ============================================================
// kernel 3: per-batch block; full z-slice in smem; edge softmax
// + aggregate + rst + BN partials.
// dynamic smem: zs[512*64] | aval[512*20] | aidx[512*20]
// ============================================================
__global__ void k_aggr(const float* __restrict__ emb, const float* __restrict__ attn_b) {
    extern __shared__ float smem[];
    float* zs   = smem;                       // 32768 floats
    float* aval = smem + NN*DD;               // 10240 floats
    int*   aidx = (int*)(smem + NN*DD + NN*TOPK);
    __shared__ float wsum[16][64];
    __shared__ float wsq[16][64];

    int tid = threadIdx.x;                    // 512 threads
    int b = blockIdx.x;
    int lane = tid & 31, w = tid >> 5;

    // load z[b] slice (128KB) via float4
    const float4* zsrc = reinterpret_cast<const float4*>(&g_z[(size_t)b * NN * DD]);
    float4* zdst = reinterpret_cast<float4*>(zs);
    #pragma unroll
    for (int i = 0; i < 16; i++) zdst[tid + i*512] = zsrc[tid + i*512];

    // alphas: thread t = dst row n
    {
        int n = tid;
        float sd = g_sdst[b*NN + n];
        float ab = __ldg(attn_b);
        float e[TOPK]; int sr[TOPK];
        float mx = -INFINITY;
        #pragma unroll
        for (int t = 0; t < TOPK; t++) {
            int i = n + t*NN;
            int s = g_topk[(i/TOPK)*TOPK + (i % TOPK)];   // reference's edge wiring
            sr[t] = s;
            float x = g_ssrc[b*NN + s] + sd + ab;
            x = x > 0.f ? x : NEG_SLOPE * x;
            e[t] = x;
            mx = fmaxf(mx, x);
        }
        float den = 0.f;
        #pragma unroll
        for (int t = 0; t < TOPK; t++) { float p = __expf(e[t]-mx); e[t] = p; den += p; }
        // use precise expf to stay bit-close to reference softmax
        den = 0.f;
        #pragma unroll
        for (int t = 0; t < TOPK; t++) { float p = expf(e[t] > 0.f ? logf(e[t]) : -INFINITY); (void)p; }
        // recompute precisely (expf) — overwrite
        den = 0.f;
        #pragma unroll
        for (int t = 0; t < TOPK; t++) {
            int i = n + t*NN;
            int s = sr[t];
            float x = g_ssrc[b*NN + s] + sd + ab;
            x = x > 0.f ? x : NEG_SLOPE * x;
            float p = expf(x - mx);
            e[t] = p; den += p;
        }
        float inv = 1.0f / den;
        #pragma unroll
        for (int t = 0; t < TOPK; t++) { aval[n*TOPK + t] = e[t]*inv; aidx[n*TOPK + t] = sr[t]; }
    }
    __syncthreads();

    // aggregate: warp w handles rows n = w*32 .. w*32+31; lane = d (and d+32)
    float ps0 = 0.f, pq0 = 0.f, ps1 = 0.f, pq1 = 0.f;
    int nbase = w * 32;
    for (int rr = 0; rr < 32; rr++) {
        int n = nbase + rr;
        float h0 = 0.f, h1 = 0.f;
        #pragma unroll
        for (int t = 0; t < TOPK; t++) {
            float a = aval[n*TOPK + t];       // broadcast
            int   s = aidx[n*TOPK + t];       // broadcast
            h0 = fmaf(a, zs[s*64 + lane], h0);
            h1 = fmaf(a, zs[s*64 + 32 + lane], h1);
        }
        float e0 = emb[n*64 + lane];
        float e1 = emb[n*64 + 32 + lane];
        float r0 = h0 * e0, r1 = h1 * e1;
        int row = b*NN + n;
        g_rst[row*64 + lane] = r0;
        g_rst[row*64 + 32 + lane] = r1;
        ps0 += r0; pq0 += r0*r0;
        ps1 += r1; pq1 += r1*r1;
    }
    wsum[w][lane] = ps0; wsum[w][lane+32] = ps1;
    wsq [w][lane] = pq0; wsq [w][lane+32] = pq1;
    __syncthreads();
    if (tid < 64) {
        float S = 0.f, Q = 0.f;
        #pragma unroll
        for (int ww = 0; ww < 16; ww++) { S += wsum[ww][tid]; Q += wsq[ww][tid]; }
        g_psum[b*64 + tid] = S;
        g_psq [b*64 + tid] = Q;
    }
}

// ============================================================
// kernel 4: BN statistics (deterministic fixed-order reduce)
// ============================================================
__global__ void k_stats(const float* __restrict__ bn_gamma) {
    int d = threadIdx.x;                  // 64 threads
    float s = 0.f, q = 0.f;
    #pragma unroll 8
    for (int j = 0; j < BB; j++) {
        s += g_psum[j*64 + d];
        q += g_psq [j*64 + d];
    }
    float mu  = s / (float)M_ROWS;
    float var = q / (float)M_ROWS - mu*mu;   // biased, matches jnp.var
    g_mu[d]    = mu;
    g_scale[d] = bn_gamma[d] / sqrtf(var + BN_EPS);
}

// ============================================================
// kernel 5: normalize + relu + output dot
// ============================================================
__global__ void k_out(const float* __restrict__ bn_beta,
                      const float* __restrict__ out_w,
                      const float* __restrict__ out_b,
                      float* __restrict__ out) {
    int w = threadIdx.x >> 5, lane = threadIdx.x & 31;
    int m = blockIdx.x * 8 + w;
    float a = 0.f;
    #pragma unroll
    for (int k = 0; k < 2; k++) {
        int dd = lane + 32*k;
        float v = (g_rst[m*64 + dd] - g_mu[dd]) * g_scale[dd] + bn_beta[dd];
        v = v > 0.f ? v : 0.f;
        a = fmaf(v, out_w[dd], a);
    }
    #pragma unroll
    for (int o = 16; o > 0; o >>= 1) a += __shfl_down_sync(0xFFFFFFFFu, a, o);
    if (lane == 0) out[m] = a + out_b[0];
}

extern "C" void kernel_launch(void* const* d_in, const int* in_sizes, int n_in,
                              void* d_out, int out_size) {
    const float* data     = (const float*)d_in[0];
    const float* emb      = (const float*)d_in[1];
    const float* fc_w     = (const float*)d_in[2];
    const float* fc_b     = (const float*)d_in[3];
    const float* attn_w   = (const float*)d_in[4];
    const float* attn_b   = (const float*)d_in[5];
    const float* bn_gamma = (const float*)d_in[6];
    const float* bn_beta  = (const float*)d_in[7];
    const float* out_w    = (const float*)d_in[8];
    const float* out_b    = (const float*)d_in[9];
    float* out = (float*)d_out;

    const int AGG_SMEM = (NN*DD + 2*NN*TOPK) * 4;   // 212992 bytes
    static int configured = 0;
    if (!configured) {
        cudaFuncSetAttribute(k_aggr, cudaFuncAttributeMaxDynamicSharedMemorySize, AGG_SMEM);
        configured = 1;
    }

    k_topk <<<NN, 512>>>(emb, attn_w);
    k_gemm <<<M_ROWS/64, 256>>>(data, fc_w, fc_b, attn_w);
    k_aggr <<<BB, 512, AGG_SMEM>>>(emb, attn_b);
    k_stats<<<1, 64>>>(bn_gamma);
    k_out  <<<M_ROWS/8, 256>>>(bn_beta, out_w, out_b, out);
}

// round 6
// speedup vs baseline: 2.2682x; 1.8706x over previous
#include <cuda_runtime.h>
#include <math.h>

#define BB 128
#define NN 512
#define FT 64
#define DD 64
#define TOPK 20
#define M_ROWS (BB*NN)          // 65536
#define NEG_SLOPE 0.2f
#define BN_EPS 1e-5f
#define TP 513                  // transposed emb pitch (odd -> conflict-free)
#define ROWS_PER_BLK 8

// ---- scratch (device globals; no allocation allowed) ----
__device__ float g_tsrc[NN];
__device__ float g_tdst[NN];
__device__ int   g_topk[NN*TOPK];
__device__ float g_z[M_ROWS*DD];
__device__ float g_ssrc[M_ROWS];
__device__ float g_sdst[M_ROWS];
__device__ float g_rst[M_ROWS*DD];
__device__ float g_psum[BB*DD];
__device__ float g_psq[BB*DD];
__device__ float g_mu[DD];
__device__ float g_scale[DD];

// ============================================================
// kernel 1: cos-sim + top-20. 64 blocks x 8 rows.
// emb staged once per block into transposed smem (pitch 513),
// so dot-loop LDS are conflict-free instead of 32-wavefront LDGs.
// Block 0 also computes the emb-half of the attention scores.
// dyn smem: emb_t[64*513] | cosv[8*512] | norm[512]
// ============================================================
__global__ void k_topk(const float* __restrict__ emb, const float* __restrict__ attn_w) {
    extern __shared__ float smem[];
    float* emb_t = smem;                       // 64*513
    float* cosv  = smem + 64*TP;               // 8*512
    float* normv = smem + 64*TP + ROWS_PER_BLK*NN;  // 512

    int tid = threadIdx.x;                     // 512 threads

    // transpose-load emb: global coalesced, smem store conflict-free (pitch 513)
    for (int i = tid; i < NN*DD; i += 512) {
        int n = i >> 6, d = i & 63;
        emb_t[d*TP + n] = emb[i];
    }
    __syncthreads();

    // per-node norm (d ascending, same accumulation order as before -> bit-stable)
    {
        float s2 = 0.f;
        #pragma unroll 16
        for (int d = 0; d < DD; d++) {
            float v = emb_t[d*TP + tid];
            s2 += v*v;
        }
        normv[tid] = sqrtf(s2);
    }

    // block 0: emb part of attention scores
    if (blockIdx.x == 0) {
        float ts = 0.f, td = 0.f;
        #pragma unroll 16
        for (int d = 0; d < DD; d++) {
            float v = emb_t[d*TP + tid];
            ts += v * attn_w[DD + d];
            td += v * attn_w[3*DD + d];
        }
        g_tsrc[tid] = ts;
        g_tdst[tid] = td;
    }
    __syncthreads();

    // 8 cos rows per block; thread = candidate m
    int nbase = blockIdx.x * ROWS_PER_BLK;
    #pragma unroll
    for (int r = 0; r < ROWS_PER_BLK; r++) {
        int n = nbase + r;
        float dot = 0.f;
        #pragma unroll 16
        for (int d = 0; d < DD; d++)
            dot += emb_t[d*TP + n] * emb_t[d*TP + tid];   // broadcast * streamed
        cosv[r*NN + tid] = dot / (normv[n] * normv[tid]);
    }
    __syncthreads();

    // 8 warps do register top-20 selection in parallel (warp w -> row w)
    int w = tid >> 5, lane = tid & 31;
    if (w >= ROWS_PER_BLK) return;
    int n = nbase + w;

    float sl[16];
    #pragma unroll
    for (int j = 0; j < 16; j++) sl[j] = cosv[w*NN + j*32 + lane];

    for (int k = 0; k < TOPK; k++) {
        // local argmax (ascending j => strict > keeps lowest index per lane)
        float bv = sl[0]; int bi = lane;
        #pragma unroll
        for (int j = 1; j < 16; j++) {
            int idx = j*32 + lane;
            if (sl[j] > bv) { bv = sl[j]; bi = idx; }
        }
        // warp all-reduce, (value desc, index asc) tie-break = jax top_k
        #pragma unroll
        for (int o = 16; o > 0; o >>= 1) {
            float ov = __shfl_xor_sync(0xFFFFFFFFu, bv, o);
            int   oi = __shfl_xor_sync(0xFFFFFFFFu, bi, o);
            if (ov > bv || (ov == bv && oi < bi)) { bv = ov; bi = oi; }
        }
        if (lane == 0) g_topk[n*TOPK + k] = bi;
        if ((bi & 31) == lane) {
            int j = bi >> 5;
            #pragma unroll
            for (int jj = 0; jj < 16; jj++) if (jj == j) sl[jj] = -INFINITY;
        }
    }
}

// ============================================================
// kernel 2: z = data @ fc_w^T + fc_b, fused with score dots.
// ============================================================
__global__ void k_gemm(const float* __restrict__ data,
                       const float* __restrict__ fc_w,
                       const float* __restrict__ fc_b,
                       const float* __restrict__ attn_w) {
    __shared__ float sw_t[64][68];   // sw_t[f][d] = fc_w[d][f]
    __shared__ float sa_t[64][68];   // sa_t[f][r] = data[row][f]
    int tid = threadIdx.x;           // 256 threads
    int rowbase = blockIdx.x * 64;

    for (int i = tid; i < 4096; i += 256) sw_t[i & 63][i >> 6] = fc_w[i];
    for (int i = tid; i < 4096; i += 256) sa_t[i & 63][i >> 6] = data[rowbase*64 + i];
    __syncthreads();

    int r0 = (tid >> 4) * 4, c0 = (tid & 15) * 4;
    float acc[4][4] = {};
    #pragma unroll
    for (int f = 0; f < 64; f++) {
        float4 av = *reinterpret_cast<const float4*>(&sa_t[f][r0]);
        float4 wv = *reinterpret_cast<const float4*>(&sw_t[f][c0]);
        float a4[4] = {av.x, av.y, av.z, av.w};
        float w4[4] = {wv.x, wv.y, wv.z, wv.w};
        #pragma unroll
        for (int i = 0; i < 4; i++)
            #pragma unroll
            for (int j = 0; j < 4; j++)
                acc[i][j] = fmaf(a4[i], w4[j], acc[i][j]);
    }

    float4 bb = *reinterpret_cast<const float4*>(&fc_b[c0]);
    float b4[4] = {bb.x, bb.y, bb.z, bb.w};
    float4 as = *reinterpret_cast<const float4*>(&attn_w[c0]);
    float4 ad = *reinterpret_cast<const float4*>(&attn_w[128 + c0]);
    float s4[4] = {as.x, as.y, as.z, as.w};
    float d4[4] = {ad.x, ad.y, ad.z, ad.w};

    float ds[4], dd[4];
    #pragma unroll
    for (int i = 0; i < 4; i++) {
        float4 o;
        float z0 = acc[i][0] + b4[0];
        float z1 = acc[i][1] + b4[1];
        float z2 = acc[i][2] + b4[2];
        float z3 = acc[i][3] + b4[3];
        o.x = z0; o.y = z1; o.z = z2; o.w = z3;
        *reinterpret_cast<float4*>(&g_z[(rowbase + r0 + i)*64 + c0]) = o;
        ds[i] = z0*s4[0] + z1*s4[1] + z2*s4[2] + z3*s4[3];
        dd[i] = z0*d4[0] + z1*d4[1] + z2*d4[2] + z3*d4[3];
    }
    #pragma unroll
    for (int o = 8; o > 0; o >>= 1) {
        #pragma unroll
        for (int i = 0; i < 4; i++) {
            ds[i] += __shfl_down_sync(0xFFFFFFFFu, ds[i], o, 16);
            dd[i] += __shfl_down_sync(0xFFFFFFFFu, dd[i], o, 16);
        }
    }
    if ((tid & 15) == 0) {
        #pragma unroll
        for (int i = 0; i < 4; i++) {
            int row = rowbase + r0 + i;
            int n = row & (NN-1);
            g_ssrc[row] = ds[i] + g_tsrc[n];
            g_sdst[row] = dd[i] + g_tdst[n];
        }
    }
}

// ============================================================
// kernel 3: per-batch block; full z-slice in smem; edge softmax
// + aggregate + rst + BN partials. (single clean softmax pass)
// dynamic smem: zs[512*64] | aval[512*20] | aidx[512*20]
// ============================================================
__global__ void k_aggr(const float* __restrict__ emb, const float* __restrict__ attn_b) {
    extern __shared__ float smem[];
    float* zs   = smem;                       // 32768 floats
    float* aval = smem + NN*DD;               // 10240 floats
    int*   aidx = (int*)(smem + NN*DD + NN*TOPK);
    __shared__ float wsum[16][64];
    __shared__ float wsq[16][64];

    int tid = threadIdx.x;                    // 512 threads
    int b = blockIdx.x;
    int lane = tid & 31, w = tid >> 5;

    // load z[b] slice (128KB) via float4
    const float4* zsrc = reinterpret_cast<const float4*>(&g_z[(size_t)b * NN * DD]);
    float4* zdst = reinterpret_cast<float4*>(zs);
    #pragma unroll
    for (int i = 0; i < 16; i++) zdst[tid + i*512] = zsrc[tid + i*512];

    // alphas: thread t = dst row n (single pass)
    {
        int n = tid;
        float sd = g_sdst[b*NN + n];
        float ab = __ldg(attn_b);
        float e[TOPK]; int sr[TOPK];
        float mx = -INFINITY;
        #pragma unroll
        for (int t = 0; t < TOPK; t++) {
            int i = n + t*NN;
            int s = g_topk[(i/TOPK)*TOPK + (i % TOPK)];   // reference's edge wiring
            sr[t] = s;
            float x = g_ssrc[b*NN + s] + sd + ab;
            x = x > 0.f ? x : NEG_SLOPE * x;              // leaky relu
            e[t] = x;
            mx = fmaxf(mx, x);
        }
        float den = 0.f;
        #pragma unroll
        for (int t = 0; t < TOPK; t++) { float p = expf(e[t] - mx); e[t] = p; den += p; }
        float inv = 1.0f / den;
        #pragma unroll
        for (int t = 0; t < TOPK; t++) { aval[n*TOPK + t] = e[t]*inv; aidx[n*TOPK + t] = sr[t]; }
    }
    __syncthreads();

    // aggregate: warp w handles rows n = w*32 .. w*32+31; lane = d (and d+32)
    float ps0 = 0.f, pq0 = 0.f, ps1 = 0.f, pq1 = 0.f;
    int nbase = w * 32;
    for (int rr = 0; rr < 32; rr++) {
        int n = nbase + rr;
        float h0 = 0.f, h1 = 0.f;
        #pragma unroll
        for (int t = 0; t < TOPK; t++) {
            float a = aval[n*TOPK + t];       // broadcast
            int   s = aidx[n*TOPK + t];       // broadcast
            h0 = fmaf(a, zs[s*64 + lane], h0);
            h1 = fmaf(a, zs[s*64 + 32 + lane], h1);
        }
        float e0 = emb[n*64 + lane];
        float e1 = emb[n*64 + 32 + lane];
        float r0 = h0 * e0, r1 = h1 * e1;
        int row = b*NN + n;
        g_rst[row*64 + lane] = r0;
        g_rst[row*64 + 32 + lane] = r1;
        ps0 += r0; pq0 += r0*r0;
        ps1 += r1; pq1 += r1*r1;
    }
    wsum[w][lane] = ps0; wsum[w][lane+32] = ps1;
    wsq [w][lane] = pq0; wsq [w][lane+32] = pq1;
    __syncthreads();
    if (tid < 64) {
        float S = 0.f, Q = 0.f;
        #pragma unroll
        for (int ww = 0; ww < 16; ww++) { S += wsum[ww][tid]; Q += wsq[ww][tid]; }
        g_psum[b*64 + tid] = S;
        g_psq [b*64 + tid] = Q;
    }
}

// ============================================================
// kernel 4: BN statistics — 64 blocks (one per d) x 128 threads
// ============================================================
__global__ void k_stats(const float* __restrict__ bn_gamma) {
    int d = blockIdx.x;
    int j = threadIdx.x;                   // 128 threads = 128 batches
    __shared__ float ss[128], sq[128];
    ss[j] = g_psum[j*64 + d];
    sq[j] = g_psq [j*64 + d];
    __syncthreads();
    #pragma unroll
    for (int st = 64; st > 0; st >>= 1) {
        if (j < st) { ss[j] += ss[j+st]; sq[j] += sq[j+st]; }
        __syncthreads();
    }
    if (j == 0) {
        float mu  = ss[0] / (float)M_ROWS;
        float var = sq[0] / (float)M_ROWS - mu*mu;   // biased, matches jnp.var
        g_mu[d]    = mu;
        g_scale[d] = bn_gamma[d] / sqrtf(var + BN_EPS);
    }
}

// ============================================================
// kernel 5: normalize + relu + output dot
// ============================================================
__global__ void k_out(const float* __restrict__ bn_beta,
                      const float* __restrict__ out_w,
                      const float* __restrict__ out_b,
                      float* __restrict__ out) {
    int w = threadIdx.x >> 5, lane = threadIdx.x & 31;
    int m = blockIdx.x * 8 + w;
    float a = 0.f;
    #pragma unroll
    for (int k = 0; k < 2; k++) {
        int dd = lane + 32*k;
        float v = (g_rst[m*64 + dd] - g_mu[dd]) * g_scale[dd] + bn_beta[dd];
        v = v > 0.f ? v : 0.f;
        a = fmaf(v, out_w[dd], a);
    }
    #pragma unroll
    for (int o = 16; o > 0; o >>= 1) a += __shfl_down_sync(0xFFFFFFFFu, a, o);
    if (lane == 0) out[m] = a + out_b[0];
}

extern "C" void kernel_launch(void* const* d_in, const int* in_sizes, int n_in,
                              void* d_out, int out_size) {
    const float* data     = (const float*)d_in[0];
    const float* emb      = (const float*)d_in[1];
    const float* fc_w     = (const float*)d_in[2];
    const float* fc_b     = (const float*)d_in[3];
    const float* attn_w   = (const float*)d_in[4];
    const float* attn_b   = (const float*)d_in[5];
    const float* bn_gamma = (const float*)d_in[6];
    const float* bn_beta  = (const float*)d_in[7];
    const float* out_w    = (const float*)d_in[8];
    const float* out_b    = (const float*)d_in[9];
    float* out = (float*)d_out;

    const int AGG_SMEM  = (NN*DD + 2*NN*TOPK) * 4;                   // 212992 bytes
    const int TOPK_SMEM = (64*TP + ROWS_PER_BLK*NN + NN) * 4;        // 149760 bytes
    static int configured = 0;
    if (!configured) {
        cudaFuncSetAttribute(k_aggr, cudaFuncAttributeMaxDynamicSharedMemorySize, AGG_SMEM);
        cudaFuncSetAttribute(k_topk, cudaFuncAttributeMaxDynamicSharedMemorySize, TOPK_SMEM);
        configured = 1;
    }

    k_topk <<<NN/ROWS_PER_BLK, 512, TOPK_SMEM>>>(emb, attn_w);
    k_gemm <<<M_ROWS/64, 256>>>(data, fc_w, fc_b, attn_w);
    k_aggr <<<BB, 512, AGG_SMEM>>>(emb, attn_b);
    k_stats<<<DD, 128>>>(bn_gamma);
    k_out  <<<M_ROWS/8, 256>>>(bn_beta, out_w, out_b, out);
}

// round 7
// speedup vs baseline: 2.6132x; 1.1521x over previous
#include <cuda_runtime.h>
#include <math.h>
#include <stdint.h>

#define BB 128
#define NN 512
#define FT 64
#define DD 64
#define TOPK 20
#define M_ROWS (BB*NN)          // 65536
#define NEG_SLOPE 0.2f
#define BN_EPS 1e-5f
#define TP 513                  // transposed emb pitch (odd -> conflict-free)
#define ROWS_PER_BLK 8
#define AP 68                   // mma smem pitch: bank = (4g+t) mod 32, conflict-free

// ---- scratch (device globals; no allocation allowed) ----
__device__ float g_tsrc[NN];
__device__ float g_tdst[NN];
__device__ int   g_topk[NN*TOPK];
__device__ float g_z[M_ROWS*DD];
__device__ float g_ssrc[M_ROWS];
__device__ float g_sdst[M_ROWS];
__device__ float g_rst[M_ROWS*DD];
__device__ float g_psum[BB*DD];
__device__ float g_psq[BB*DD];
__device__ float g_mu[DD];
__device__ float g_scale[DD];
__device__ unsigned int g_ctr = 0;

__device__ __forceinline__ uint32_t f2tf32(float x) {
    uint32_t r;
    asm("cvt.rna.tf32.f32 %0, %1;" : "=r"(r) : "f"(x));
    return r;
}

#define MMA_TF32(ac, a0,a1,a2,a3, b0,b1) \
    asm volatile("mma.sync.aligned.m16n8k8.row.col.f32.tf32.tf32.f32 " \
        "{%0,%1,%2,%3}, {%4,%5,%6,%7}, {%8,%9}, {%0,%1,%2,%3};" \
        : "+f"((ac)[0]), "+f"((ac)[1]), "+f"((ac)[2]), "+f"((ac)[3]) \
        : "r"(a0), "r"(a1), "r"(a2), "r"(a3), "r"(b0), "r"(b1))

// ============================================================
// kernel 1: cos-sim + top-20. 64 blocks x 8 rows.
// Block 0 also computes the emb-half of the attention scores.
// ============================================================
__global__ void k_topk(const float* __restrict__ emb, const float* __restrict__ attn_w) {
    extern __shared__ float smem[];
    float* emb_t = smem;                       // 64*513
    float* cosv  = smem + 64*TP;               // 8*512
    float* normv = smem + 64*TP + ROWS_PER_BLK*NN;  // 512

    int tid = threadIdx.x;                     // 512 threads

    for (int i = tid; i < NN*DD; i += 512) {
        int n = i >> 6, d = i & 63;
        emb_t[d*TP + n] = emb[i];
    }
    __syncthreads();

    {
        float s2 = 0.f;
        #pragma unroll 16
        for (int d = 0; d < DD; d++) {
            float v = emb_t[d*TP + tid];
            s2 += v*v;
        }
        normv[tid] = sqrtf(s2);
    }

    if (blockIdx.x == 0) {
        float ts = 0.f, td = 0.f;
        #pragma unroll 16
        for (int d = 0; d < DD; d++) {
            float v = emb_t[d*TP + tid];
            ts += v * attn_w[DD + d];
            td += v * attn_w[3*DD + d];
        }
        g_tsrc[tid] = ts;
        g_tdst[tid] = td;
    }
    __syncthreads();

    int nbase = blockIdx.x * ROWS_PER_BLK;
    #pragma unroll
    for (int r = 0; r < ROWS_PER_BLK; r++) {
        int n = nbase + r;
        float dot = 0.f;
        #pragma unroll 16
        for (int d = 0; d < DD; d++)
            dot += emb_t[d*TP + n] * emb_t[d*TP + tid];
        cosv[r*NN + tid] = dot / (normv[n] * normv[tid]);
    }
    __syncthreads();

    int w = tid >> 5, lane = tid & 31;
    if (w >= ROWS_PER_BLK) return;
    int n = nbase + w;

    float sl[16];
    #pragma unroll
    for (int j = 0; j < 16; j++) sl[j] = cosv[w*NN + j*32 + lane];

    for (int k = 0; k < TOPK; k++) {
        float bv = sl[0]; int bi = lane;
        #pragma unroll
        for (int j = 1; j < 16; j++) {
            int idx = j*32 + lane;
            if (sl[j] > bv) { bv = sl[j]; bi = idx; }
        }
        #pragma unroll
        for (int o = 16; o > 0; o >>= 1) {
            float ov = __shfl_xor_sync(0xFFFFFFFFu, bv, o);
            int   oi = __shfl_xor_sync(0xFFFFFFFFu, bi, o);
            if (ov > bv || (ov == bv && oi < bi)) { bv = ov; bi = oi; }
        }
        if (lane == 0) g_topk[n*TOPK + k] = bi;
        if ((bi & 31) == lane) {
            int j = bi >> 5;
            #pragma unroll
            for (int jj = 0; jj < 16; jj++) if (jj == j) sl[jj] = -INFINITY;
        }
    }
}

// ============================================================
// kernel 2: z = data @ fc_w^T + fc_b via split-tf32 mma,
// fused with score dots.  512 blocks x 256 thr; 128 rows/block.
// smem: Ah[128*68] Al[128*68] Bh[64*68] Bl[64*68]
// ============================================================
__global__ void k_gemm(const float* __restrict__ data,
                       const float* __restrict__ fc_w,
                       const float* __restrict__ fc_b,
                       const float* __restrict__ attn_w) {
    extern __shared__ float gs[];
    float* sAh = gs;
    float* sAl = gs + 128*AP;
    float* sBh = gs + 2*128*AP;
    float* sBl = sBh + 64*AP;

    int tid = threadIdx.x;           // 256
    int rowbase = blockIdx.x * 128;

    // load + split A (data tile 128x64) via float4
    {
        const float4* src = reinterpret_cast<const float4*>(data + (size_t)rowbase*64);
        #pragma unroll
        for (int k = 0; k < 8; k++) {
            int i4 = tid + k*256;            // float4 index, 2048 total
            float4 v = src[i4];
            float a[4] = {v.x, v.y, v.z, v.w};
            int base = i4 * 4;
            int r = base >> 6, c = base & 63;
            #pragma unroll
            for (int e = 0; e < 4; e++) {
                uint32_t hb = f2tf32(a[e]);
                float hf = __uint_as_float(hb);
                float lo = a[e] - hf;
                sAh[r*AP + c + e] = hf;
                sAl[r*AP + c + e] = __uint_as_float(f2tf32(lo));
            }
        }
    }
    // load + split B (fc_w 64x64, [d][f])
    {
        const float4* src = reinterpret_cast<const float4*>(fc_w);
        #pragma unroll
        for (int k = 0; k < 4; k++) {
            int i4 = tid + k*256;            // 1024 total
            float4 v = src[i4];
            float a[4] = {v.x, v.y, v.z, v.w};
            int base = i4 * 4;
            int r = base >> 6, c = base & 63;
            #pragma unroll
            for (int e = 0; e < 4; e++) {
                uint32_t hb = f2tf32(a[e]);
                float hf = __uint_as_float(hb);
                float lo = a[e] - hf;
                sBh[r*AP + c + e] = hf;
                sBl[r*AP + c + e] = __uint_as_float(f2tf32(lo));
            }
        }
    }
    __syncthreads();

    int w = tid >> 5, lane = tid & 31;
    int g = lane >> 2, t = lane & 3;
    int warp_m = w * 16;

    float acc[8][4] = {};
    #pragma unroll
    for (int kk = 0; kk < 8; kk++) {
        int c = kk*8 + t;
        int r0 = warp_m + g;
        uint32_t ah0 = __float_as_uint(sAh[r0*AP + c]);
        uint32_t ah1 = __float_as_uint(sAh[(r0+8)*AP + c]);
        uint32_t ah2 = __float_as_uint(sAh[r0*AP + c + 4]);
        uint32_t ah3 = __float_as_uint(sAh[(r0+8)*AP + c + 4]);
        uint32_t al0 = __float_as_uint(sAl[r0*AP + c]);
        uint32_t al1 = __float_as_uint(sAl[(r0+8)*AP + c]);
        uint32_t al2 = __float_as_uint(sAl[r0*AP + c + 4]);
        uint32_t al3 = __float_as_uint(sAl[(r0+8)*AP + c + 4]);
        #pragma unroll
        for (int j = 0; j < 8; j++) {
            int bn = j*8 + g;
            uint32_t bh0 = __float_as_uint(sBh[bn*AP + c]);
            uint32_t bh1 = __float_as_uint(sBh[bn*AP + c + 4]);
            uint32_t bl0 = __float_as_uint(sBl[bn*AP + c]);
            uint32_t bl1 = __float_as_uint(sBl[bn*AP + c + 4]);
            MMA_TF32(acc[j], ah0, ah1, ah2, ah3, bh0, bh1);   // hi*hi
            MMA_TF32(acc[j], al0, al1, al2, al3, bh0, bh1);   // lo*hi
            MMA_TF32(acc[j], ah0, ah1, ah2, ah3, bl0, bl1);   // hi*lo
        }
    }

    // epilogue: bias, store z, fused score dots
    int row0 = rowbase + warp_m + g;
    int row1 = row0 + 8;
    float ds0 = 0.f, dd0 = 0.f, ds1 = 0.f, dd1 = 0.f;
    #pragma unroll
    for (int j = 0; j < 8; j++) {
        int n0 = j*8 + 2*t;
        float b0 = __ldg(&fc_b[n0]), b1 = __ldg(&fc_b[n0+1]);
        float z00 = acc[j][0] + b0, z01 = acc[j][1] + b1;
        float z10 = acc[j][2] + b0, z11 = acc[j][3] + b1;
        float2 v0; v0.x = z00; v0.y = z01;
        float2 v1; v1.x = z10; v1.y = z11;
        *reinterpret_cast<float2*>(&g_z[(size_t)row0*64 + n0]) = v0;
        *reinterpret_cast<float2*>(&g_z[(size_t)row1*64 + n0]) = v1;
        float as0 = __ldg(&attn_w[n0]),     as1 = __ldg(&attn_w[n0+1]);
        float ad0 = __ldg(&attn_w[128+n0]), ad1 = __ldg(&attn_w[128+n0+1]);
        ds0 += z00*as0 + z01*as1;  dd0 += z00*ad0 + z01*ad1;
        ds1 += z10*as0 + z11*as1;  dd1 += z10*ad0 + z11*ad1;
    }
    // reduce over t (4 lanes)
    #pragma unroll
    for (int o = 2; o > 0; o >>= 1) {
        ds0 += __shfl_down_sync(0xFFFFFFFFu, ds0, o, 4);
        dd0 += __shfl_down_sync(0xFFFFFFFFu, dd0, o, 4);
        ds1 += __shfl_down_sync(0xFFFFFFFFu, ds1, o, 4);
        dd1 += __shfl_down_sync(0xFFFFFFFFu, dd1, o, 4);
    }
    if (t == 0) {
        int n0 = row0 & (NN-1), n1 = row1 & (NN-1);
        g_ssrc[row0] = ds0 + g_tsrc[n0];
        g_sdst[row0] = dd0 + g_tdst[n0];
        g_ssrc[row1] = ds1 + g_tsrc[n1];
        g_sdst[row1] = dd1 + g_tdst[n1];
    }
}

// ============================================================
// kernel 3: per-batch block; full z-slice in smem; edge softmax
// + aggregate + rst + BN partials. Last block computes BN stats
// (threadfence + atomic counter; fixed-order reduce = deterministic).
// dynamic smem: zs[512*64] | aval[512*20] | aidx[512*20]
// ============================================================
__global__ void k_aggr(const float* __restrict__ emb, const float* __restrict__ attn_b,
                       const float* __restrict__ bn_gamma) {
    extern __shared__ float smem[];
    float* zs   = smem;                       // 32768 floats
    float* aval = smem + NN*DD;               // 10240 floats
    int*   aidx = (int*)(smem + NN*DD + NN*TOPK);
    __shared__ float wsum[16][64];
    __shared__ float wsq[16][64];
    __shared__ unsigned int s_last;

    int tid = threadIdx.x;                    // 512 threads
    int b = blockIdx.x;
    int lane = tid & 31, w = tid >> 5;

    // load z[b] slice (128KB) via float4
    const float4* zsrc = reinterpret_cast<const float4*>(&g_z[(size_t)b * NN * DD]);
    float4* zdst = reinterpret_cast<float4*>(zs);
    #pragma unroll
    for (int i = 0; i < 16; i++) zdst[tid + i*512] = zsrc[tid + i*512];

    // alphas: thread t = dst row n (single pass)
    {
        int n = tid;
        float sd = g_sdst[b*NN + n];
        float ab = __ldg(attn_b);
        float e[TOPK]; int sr[TOPK];
        float mx = -INFINITY;
        #pragma unroll
        for (int t = 0; t < TOPK; t++) {
            int i = n + t*NN;
            int s = g_topk[(i/TOPK)*TOPK + (i % TOPK)];   // reference's edge wiring
            sr[t] = s;
            float x = g_ssrc[b*NN + s] + sd + ab;
            x = x > 0.f ? x : NEG_SLOPE * x;              // leaky relu
            e[t] = x;
            mx = fmaxf(mx, x);
        }
        float den = 0.f;
        #pragma unroll
        for (int t = 0; t < TOPK; t++) { float p = expf(e[t] - mx); e[t] = p; den += p; }
        float inv = 1.0f / den;
        #pragma unroll
        for (int t = 0; t < TOPK; t++) { aval[n*TOPK + t] = e[t]*inv; aidx[n*TOPK + t] = sr[t]; }
    }
    __syncthreads();

    // aggregate: warp w handles rows n = w*32 .. w*32+31; lane = d (and d+32)
    float ps0 = 0.f, pq0 = 0.f, ps1 = 0.f, pq1 = 0.f;
    int nbase = w * 32;
    for (int rr = 0; rr < 32; rr++) {
        int n = nbase + rr;
        float h0 = 0.f, h1 = 0.f;
        #pragma unroll
        for (int t = 0; t < TOPK; t++) {
            float a = aval[n*TOPK + t];       // broadcast
            int   s = aidx[n*TOPK + t];       // broadcast
            h0 = fmaf(a, zs[s*64 + lane], h0);
            h1 = fmaf(a, zs[s*64 + 32 + lane], h1);
        }
        float e0 = emb[n*64 + lane];
        float e1 = emb[n*64 + 32 + lane];
        float r0 = h0 * e0, r1 = h1 * e1;
        int row = b*NN + n;
        g_rst[row*64 + lane] = r0;
        g_rst[row*64 + 32 + lane] = r1;
        ps0 += r0; pq0 += r0*r0;
        ps1 += r1; pq1 += r1*r1;
    }
    wsum[w][lane] = ps0; wsum[w][lane+32] = ps1;
    wsq [w][lane] = pq0; wsq [w][lane+32] = pq1;
    __syncthreads();
    if (tid < 64) {
        float S = 0.f, Q = 0.f;
        #pragma unroll
        for (int ww = 0; ww < 16; ww++) { S += wsum[ww][tid]; Q += wsq[ww][tid]; }
        g_psum[b*64 + tid] = S;
        g_psq [b*64 + tid] = Q;
        __threadfence();                       // writer-side fence (device scope)
    }
    __syncthreads();
    if (tid == 0) s_last = (atomicAdd(&g_ctr, 1u) == BB - 1u);
    __syncthreads();

    if (s_last) {
        if (tid == 0) g_ctr = 0;               // reset for next graph replay
        // 8 groups x 64 d; fixed ascending order -> deterministic
        int d = tid & 63, grp = tid >> 6;
        float s = 0.f, q = 0.f;
        #pragma unroll
        for (int jj = 0; jj < 16; jj++) {
            int j = grp*16 + jj;
            s += g_psum[j*64 + d];
            q += g_psq [j*64 + d];
        }
        wsum[grp][d] = s; wsq[grp][d] = q;
        __syncthreads();
        if (tid < 64) {
            float S = 0.f, Q = 0.f;
            #pragma unroll
            for (int gg = 0; gg < 8; gg++) { S += wsum[gg][tid]; Q += wsq[gg][tid]; }
            float mu  = S / (float)M_ROWS;
            float var = Q / (float)M_ROWS - mu*mu;   // biased, matches jnp.var
            g_mu[tid]    = mu;
            g_scale[tid] = bn_gamma[tid] / sqrtf(var + BN_EPS);
        }
    }
}

// ============================================================
// kernel 4: normalize + relu + output dot
// ============================================================
__global__ void k_out(const float* __restrict__ bn_beta,
                      const float* __restrict__ out_w,
                      const float* __restrict__ out_b,
                      float* __restrict__ out) {
    int w = threadIdx.x >> 5, lane = threadIdx.x & 31;
    int m = blockIdx.x * 8 + w;
    float a = 0.f;
    #pragma unroll
    for (int k = 0; k < 2; k++) {
        int dd = lane + 32*k;
        float v = (g_rst[m*64 + dd] - g_mu[dd]) * g_scale[dd] + bn_beta[dd];
        v = v > 0.f ? v : 0.f;
        a = fmaf(v, out_w[dd], a);
    }
    #pragma unroll
    for (int o = 16; o > 0; o >>= 1) a += __shfl_down_sync(0xFFFFFFFFu, a, o);
    if (lane == 0) out[m] = a + out_b[0];
}

extern "C" void kernel_launch(void* const* d_in, const int* in_sizes, int n_in,
                              void* d_out, int out_size) {
    const float* data     = (const float*)d_in[0];
    const float* emb      = (const float*)d_in[1];
    const float* fc_w     = (const float*)d_in[2];
    const float* fc_b     = (const float*)d_in[3];
    const float* attn_w   = (const float*)d_in[4];
    const float* attn_b   = (const float*)d_in[5];
    const float* bn_gamma = (const float*)d_in[6];
    const float* bn_beta  = (const float*)d_in[7];
    const float* out_w    = (const float*)d_in[8];
    const float* out_b    = (const float*)d_in[9];
    float* out = (float*)d_out;

    const int AGG_SMEM  = (NN*DD + 2*NN*TOPK) * 4;                   // 212992 bytes
    const int TOPK_SMEM = (64*TP + ROWS_PER_BLK*NN + NN) * 4;        // 149760 bytes
    const int GEMM_SMEM = (2*128*AP + 2*64*AP) * 4;                  // 104448 bytes
    static int configured = 0;
    if (!configured) {
        cudaFuncSetAttribute(k_aggr, cudaFuncAttributeMaxDynamicSharedMemorySize, AGG_SMEM);
        cudaFuncSetAttribute(k_topk, cudaFuncAttributeMaxDynamicSharedMemorySize, TOPK_SMEM);
        cudaFuncSetAttribute(k_gemm, cudaFuncAttributeMaxDynamicSharedMemorySize, GEMM_SMEM);
        configured = 1;
    }

    k_topk <<<NN/ROWS_PER_BLK, 512, TOPK_SMEM>>>(emb, attn_w);
    k_gemm <<<M_ROWS/128, 256, GEMM_SMEM>>>(data, fc_w, fc_b, attn_w);
    k_aggr <<<BB, 512, AGG_SMEM>>>(emb, attn_b, bn_gamma);
    k_out  <<<M_ROWS/8, 256>>>(bn_beta, out_w, out_b, out);
}

// round 8
// speedup vs baseline: 3.0119x; 1.1526x over previous
#include <cuda_runtime.h>
#include <math.h>
#include <stdint.h>

#define BB 128
#define NN 512
#define FT 64
#define DD 64
#define TOPK 20
#define M_ROWS (BB*NN)          // 65536
#define NEG_SLOPE 0.2f
#define BN_EPS 1e-5f
#define TP 513                  // transposed emb pitch (odd -> conflict-free)
#define ROWS_PER_BLK 8
#define AP 68                   // mma smem pitch

// ---- scratch (device globals; no allocation allowed) ----
__device__ float g_tsrc[NN];
__device__ float g_tdst[NN];
__device__ int   g_topk[NN*TOPK];
__device__ float g_z[M_ROWS*DD];
__device__ float g_ssrc[M_ROWS];
__device__ float g_sdst[M_ROWS];
__device__ float g_psum[BB*DD];
__device__ float g_psq[BB*DD];
__device__ float g_mu[DD];
__device__ float g_scale[DD];
__device__ unsigned int g_ctr  = 0;
__device__ unsigned int g_ctr2 = 0;
__device__ unsigned int g_done = 0;

__device__ __forceinline__ uint32_t f2tf32(float x) {
    uint32_t r;
    asm("cvt.rna.tf32.f32 %0, %1;" : "=r"(r) : "f"(x));
    return r;
}

#define MMA_TF32(ac, a0,a1,a2,a3, b0,b1) \
    asm volatile("mma.sync.aligned.m16n8k8.row.col.f32.tf32.tf32.f32 " \
        "{%0,%1,%2,%3}, {%4,%5,%6,%7}, {%8,%9}, {%0,%1,%2,%3};" \
        : "+f"((ac)[0]), "+f"((ac)[1]), "+f"((ac)[2]), "+f"((ac)[3]) \
        : "r"(a0), "r"(a1), "r"(a2), "r"(a3), "r"(b0), "r"(b1))

// ============================================================
// kernel 1: cos-sim + top-20. 64 blocks x 8 rows.
// Block 0 also computes the emb-half of the attention scores.
// Runs CONCURRENTLY with k_gemm (no shared data).
// ============================================================
__global__ void k_topk(const float* __restrict__ emb, const float* __restrict__ attn_w) {
    extern __shared__ float smem[];
    float* emb_t = smem;                       // 64*513
    float* cosv  = smem + 64*TP;               // 8*512
    float* normv = smem + 64*TP + ROWS_PER_BLK*NN;  // 512

    int tid = threadIdx.x;                     // 512 threads

    for (int i = tid; i < NN*DD; i += 512) {
        int n = i >> 6, d = i & 63;
        emb_t[d*TP + n] = emb[i];
    }
    __syncthreads();

    {
        float s2 = 0.f;
        #pragma unroll 16
        for (int d = 0; d < DD; d++) {
            float v = emb_t[d*TP + tid];
            s2 += v*v;
        }
        normv[tid] = sqrtf(s2);
    }

    if (blockIdx.x == 0) {
        float ts = 0.f, td = 0.f;
        #pragma unroll 16
        for (int d = 0; d < DD; d++) {
            float v = emb_t[d*TP + tid];
            ts += v * attn_w[DD + d];
            td += v * attn_w[3*DD + d];
        }
        g_tsrc[tid] = ts;
        g_tdst[tid] = td;
    }
    __syncthreads();

    int nbase = blockIdx.x * ROWS_PER_BLK;
    #pragma unroll
    for (int r = 0; r < ROWS_PER_BLK; r++) {
        int n = nbase + r;
        float dot = 0.f;
        #pragma unroll 16
        for (int d = 0; d < DD; d++)
            dot += emb_t[d*TP + n] * emb_t[d*TP + tid];
        cosv[r*NN + tid] = dot / (normv[n] * normv[tid]);
    }
    __syncthreads();

    int w = tid >> 5, lane = tid & 31;
    if (w >= ROWS_PER_BLK) return;
    int n = nbase + w;

    float sl[16];
    #pragma unroll
    for (int j = 0; j < 16; j++) sl[j] = cosv[w*NN + j*32 + lane];

    for (int k = 0; k < TOPK; k++) {
        float bv = sl[0]; int bi = lane;
        #pragma unroll
        for (int j = 1; j < 16; j++) {
            int idx = j*32 + lane;
            if (sl[j] > bv) { bv = sl[j]; bi = idx; }
        }
        #pragma unroll
        for (int o = 16; o > 0; o >>= 1) {
            float ov = __shfl_xor_sync(0xFFFFFFFFu, bv, o);
            int   oi = __shfl_xor_sync(0xFFFFFFFFu, bi, o);
            if (ov > bv || (ov == bv && oi < bi)) { bv = ov; bi = oi; }
        }
        if (lane == 0) g_topk[n*TOPK + k] = bi;
        if ((bi & 31) == lane) {
            int j = bi >> 5;
            #pragma unroll
            for (int jj = 0; jj < 16; jj++) if (jj == j) sl[jj] = -INFINITY;
        }
    }
}

// ============================================================
// kernel 2: z = data @ fc_w^T + fc_b via split-tf32 mma,
// fused with z-part of score dots (tsrc/tdst added later in k_aggr,
// so this kernel is fully independent of k_topk).
// ============================================================
__global__ void k_gemm(const float* __restrict__ data,
                       const float* __restrict__ fc_w,
                       const float* __restrict__ fc_b,
                       const float* __restrict__ attn_w) {
    extern __shared__ float gs[];
    float* sAh = gs;
    float* sAl = gs + 128*AP;
    float* sBh = gs + 2*128*AP;
    float* sBl = sBh + 64*AP;

    int tid = threadIdx.x;           // 256
    int rowbase = blockIdx.x * 128;

    {
        const float4* src = reinterpret_cast<const float4*>(data + (size_t)rowbase*64);
        #pragma unroll
        for (int k = 0; k < 8; k++) {
            int i4 = tid + k*256;
            float4 v = src[i4];
            float a[4] = {v.x, v.y, v.z, v.w};
            int base = i4 * 4;
            int r = base >> 6, c = base & 63;
            #pragma unroll
            for (int e = 0; e < 4; e++) {
                uint32_t hb = f2tf32(a[e]);
                float hf = __uint_as_float(hb);
                float lo = a[e] - hf;
                sAh[r*AP + c + e] = hf;
                sAl[r*AP + c + e] = __uint_as_float(f2tf32(lo));
            }
        }
    }
    {
        const float4* src = reinterpret_cast<const float4*>(fc_w);
        #pragma unroll
        for (int k = 0; k < 4; k++) {
            int i4 = tid + k*256;
            float4 v = src[i4];
            float a[4] = {v.x, v.y, v.z, v.w};
            int base = i4 * 4;
            int r = base >> 6, c = base & 63;
            #pragma unroll
            for (int e = 0; e < 4; e++) {
                uint32_t hb = f2tf32(a[e]);
                float hf = __uint_as_float(hb);
                float lo = a[e] - hf;
                sBh[r*AP + c + e] = hf;
                sBl[r*AP + c + e] = __uint_as_float(f2tf32(lo));
            }
        }
    }
    __syncthreads();

    int w = tid >> 5, lane = tid & 31;
    int g = lane >> 2, t = lane & 3;
    int warp_m = w * 16;

    float acc[8][4] = {};
    #pragma unroll
    for (int kk = 0; kk < 8; kk++) {
        int c = kk*8 + t;
        int r0 = warp_m + g;
        uint32_t ah0 = __float_as_uint(sAh[r0*AP + c]);
        uint32_t ah1 = __float_as_uint(sAh[(r0+8)*AP + c]);
        uint32_t ah2 = __float_as_uint(sAh[r0*AP + c + 4]);
        uint32_t ah3 = __float_as_uint(sAh[(r0+8)*AP + c + 4]);
        uint32_t al0 = __float_as_uint(sAl[r0*AP + c]);
        uint32_t al1 = __float_as_uint(sAl[(r0+8)*AP + c]);
        uint32_t al2 = __float_as_uint(sAl[r0*AP + c + 4]);
        uint32_t al3 = __float_as_uint(sAl[(r0+8)*AP + c + 4]);
        #pragma unroll
        for (int j = 0; j < 8; j++) {
            int bn = j*8 + g;
            uint32_t bh0 = __float_as_uint(sBh[bn*AP + c]);
            uint32_t bh1 = __float_as_uint(sBh[bn*AP + c + 4]);
            uint32_t bl0 = __float_as_uint(sBl[bn*AP + c]);
            uint32_t bl1 = __float_as_uint(sBl[bn*AP + c + 4]);
            MMA_TF32(acc[j], ah0, ah1, ah2, ah3, bh0, bh1);   // hi*hi
            MMA_TF32(acc[j], al0, al1, al2, al3, bh0, bh1);   // lo*hi
            MMA_TF32(acc[j], ah0, ah1, ah2, ah3, bl0, bl1);   // hi*lo
        }
    }

    int row0 = rowbase + warp_m + g;
    int row1 = row0 + 8;
    float ds0 = 0.f, dd0 = 0.f, ds1 = 0.f, dd1 = 0.f;
    #pragma unroll
    for (int j = 0; j < 8; j++) {
        int n0 = j*8 + 2*t;
        float b0 = __ldg(&fc_b[n0]), b1 = __ldg(&fc_b[n0+1]);
        float z00 = acc[j][0] + b0, z01 = acc[j][1] + b1;
        float z10 = acc[j][2] + b0, z11 = acc[j][3] + b1;
        float2 v0; v0.x = z00; v0.y = z01;
        float2 v1; v1.x = z10; v1.y = z11;
        *reinterpret_cast<float2*>(&g_z[(size_t)row0*64 + n0]) = v0;
        *reinterpret_cast<float2*>(&g_z[(size_t)row1*64 + n0]) = v1;
        float as0 = __ldg(&attn_w[n0]),     as1 = __ldg(&attn_w[n0+1]);
        float ad0 = __ldg(&attn_w[128+n0]), ad1 = __ldg(&attn_w[128+n0+1]);
        ds0 += z00*as0 + z01*as1;  dd0 += z00*ad0 + z01*ad1;
        ds1 += z10*as0 + z11*as1;  dd1 += z10*ad0 + z11*ad1;
    }
    #pragma unroll
    for (int o = 2; o > 0; o >>= 1) {
        ds0 += __shfl_down_sync(0xFFFFFFFFu, ds0, o, 4);
        dd0 += __shfl_down_sync(0xFFFFFFFFu, dd0, o, 4);
        ds1 += __shfl_down_sync(0xFFFFFFFFu, ds1, o, 4);
        dd1 += __shfl_down_sync(0xFFFFFFFFu, dd1, o, 4);
    }
    if (t == 0) {
        g_ssrc[row0] = ds0;   // z-part only; tsrc/tdst folded in k_aggr
        g_sdst[row0] = dd0;
        g_ssrc[row1] = ds1;
        g_sdst[row1] = dd1;
    }
}

// ============================================================
// kernel 3: per-batch block (128 blocks = 1 wave, all co-resident).
// softmax + aggregate + BN partials; software grid-sync; then
// BN-normalize + relu + out-projection straight from registers.
// dynamic smem: zs[512*64] | aval[512*20] | aidx[512*20]
// ============================================================
__global__ void k_aggr(const float* __restrict__ emb, const float* __restrict__ attn_b,
                       const float* __restrict__ bn_gamma, const float* __restrict__ bn_beta,
                       const float* __restrict__ out_w, const float* __restrict__ out_b,
                       float* __restrict__ out) {
    extern __shared__ float smem[];
    float* zs   = smem;                       // 32768 floats
    float* aval = smem + NN*DD;               // 10240 floats
    int*   aidx = (int*)(smem + NN*DD + NN*TOPK);
    __shared__ float wsum[16][64];
    __shared__ float wsq[16][64];
    __shared__ float s_ssrc[NN];              // ssrc_z + tsrc, this batch
    __shared__ unsigned int s_last;

    int tid = threadIdx.x;                    // 512 threads
    int b = blockIdx.x;
    int lane = tid & 31, w = tid >> 5;

    // load z[b] slice (128KB) via float4
    const float4* zsrc = reinterpret_cast<const float4*>(&g_z[(size_t)b * NN * DD]);
    float4* zdst = reinterpret_cast<float4*>(zs);
    #pragma unroll
    for (int i = 0; i < 16; i++) zdst[tid + i*512] = zsrc[tid + i*512];

    s_ssrc[tid] = g_ssrc[b*NN + tid] + g_tsrc[tid];
    __syncthreads();

    // alphas: thread t = dst row n
    {
        int n = tid;
        float sd = g_sdst[b*NN + n] + g_tdst[n] + __ldg(attn_b);
        float e[TOPK]; int sr[TOPK];
        float mx = -INFINITY;
        #pragma unroll
        for (int t = 0; t < TOPK; t++) {
            int i = n + t*NN;
            int s = g_topk[(i/TOPK)*TOPK + (i % TOPK)];   // reference's edge wiring
            sr[t] = s;
            float x = s_ssrc[s] + sd;
            x = x > 0.f ? x : NEG_SLOPE * x;              // leaky relu
            e[t] = x;
            mx = fmaxf(mx, x);
        }
        float den = 0.f;
        #pragma unroll
        for (int t = 0; t < TOPK; t++) { float p = expf(e[t] - mx); e[t] = p; den += p; }
        float inv = 1.0f / den;
        #pragma unroll
        for (int t = 0; t < TOPK; t++) { aval[n*TOPK + t] = e[t]*inv; aidx[n*TOPK + t] = sr[t]; }
    }
    __syncthreads();

    // aggregate: warp w -> rows n = w*32..w*32+31; lane = d (and d+32).
    // rst kept in registers.
    float rr0[32], rr1[32];
    float ps0 = 0.f, pq0 = 0.f, ps1 = 0.f, pq1 = 0.f;
    int nbase = w * 32;
    #pragma unroll
    for (int rr = 0; rr < 32; rr++) {
        int n = nbase + rr;
        float h0 = 0.f, h1 = 0.f;
        #pragma unroll
        for (int t = 0; t < TOPK; t++) {
            float a = aval[n*TOPK + t];       // broadcast
            int   s = aidx[n*TOPK + t];       // broadcast
            h0 = fmaf(a, zs[s*64 + lane], h0);
            h1 = fmaf(a, zs[s*64 + 32 + lane], h1);
        }
        float e0 = emb[n*64 + lane];
        float e1 = emb[n*64 + 32 + lane];
        float r0 = h0 * e0, r1 = h1 * e1;
        rr0[rr] = r0; rr1[rr] = r1;
        ps0 += r0; pq0 += r0*r0;
        ps1 += r1; pq1 += r1*r1;
    }
    wsum[w][lane] = ps0; wsum[w][lane+32] = ps1;
    wsq [w][lane] = pq0; wsq [w][lane+32] = pq1;
    __syncthreads();
    if (tid < 64) {
        float S = 0.f, Q = 0.f;
        #pragma unroll
        for (int ww = 0; ww < 16; ww++) { S += wsum[ww][tid]; Q += wsq[ww][tid]; }
        g_psum[b*64 + tid] = S;
        g_psq [b*64 + tid] = Q;
    }
    __threadfence();
    __syncthreads();
    if (tid == 0) s_last = (atomicAdd(&g_ctr, 1u) == BB - 1u) ? 1u : 0u;
    __syncthreads();

    if (s_last) {
        __threadfence();                       // acquire: all blocks' psum visible
        int d = tid & 63, grp = tid >> 6;      // 8 groups x 64 d
        float s = 0.f, q = 0.f;
        #pragma unroll
        for (int jj = 0; jj < 16; jj++) {
            int j = grp*16 + jj;
            s += g_psum[j*64 + d];
            q += g_psq [j*64 + d];
        }
        __syncthreads();                       // wsum free for reuse
        wsum[grp][d] = s; wsq[grp][d] = q;
        __syncthreads();
        if (tid < 64) {
            float S = 0.f, Q = 0.f;
            #pragma unroll
            for (int gg = 0; gg < 8; gg++) { S += wsum[gg][tid]; Q += wsq[gg][tid]; }
            float mu  = S / (float)M_ROWS;
            float var = Q / (float)M_ROWS - mu*mu;   // biased, matches jnp.var
            g_mu[tid]    = mu;
            g_scale[tid] = bn_gamma[tid] / sqrtf(var + BN_EPS);
        }
        __threadfence();
        __syncthreads();
        if (tid == 0) atomicExch(&g_done, 1u);
    }

    // grid-wide wait: all 128 blocks co-resident (1/SM, 128 <= 148 SMs)
    if (tid == 0) {
        while (atomicAdd(&g_done, 0u) == 0u) { }
    }
    __syncthreads();
    __threadfence();

    // fused BN-normalize + relu + out projection from registers
    {
        float mu0 = g_mu[lane],       mu1 = g_mu[lane+32];
        float sc0 = g_scale[lane],    sc1 = g_scale[lane+32];
        float bt0 = bn_beta[lane],    bt1 = bn_beta[lane+32];
        float ow0 = out_w[lane],      ow1 = out_w[lane+32];
        float ob  = __ldg(out_b);
        #pragma unroll
        for (int rr = 0; rr < 32; rr++) {
            float v0 = (rr0[rr] - mu0) * sc0 + bt0;
            float v1 = (rr1[rr] - mu1) * sc1 + bt1;
            v0 = v0 > 0.f ? v0 : 0.f;
            v1 = v1 > 0.f ? v1 : 0.f;
            float a = v0*ow0 + v1*ow1;
            #pragma unroll
            for (int o = 16; o > 0; o >>= 1) a += __shfl_down_sync(0xFFFFFFFFu, a, o);
            if (lane == 0) out[b*NN + nbase + rr] = a + ob;
        }
    }

    // reset counters for next graph replay (last block to depart)
    __syncthreads();
    if (tid == 0) {
        if (atomicAdd(&g_ctr2, 1u) == BB - 1u) {
            g_ctr = 0; g_ctr2 = 0; g_done = 0;
            __threadfence();
        }
    }
}

extern "C" void kernel_launch(void* const* d_in, const int* in_sizes, int n_in,
                              void* d_out, int out_size) {
    const float* data     = (const float*)d_in[0];
    const float* emb      = (const float*)d_in[1];
    const float* fc_w     = (const float*)d_in[2];
    const float* fc_b     = (const float*)d_in[3];
    const float* attn_w   = (const float*)d_in[4];
    const float* attn_b   = (const float*)d_in[5];
    const float* bn_gamma = (const float*)d_in[6];
    const float* bn_beta  = (const float*)d_in[7];
    const float* out_w    = (const float*)d_in[8];
    const float* out_b    = (const float*)d_in[9];
    float* out = (float*)d_out;

    const int AGG_SMEM  = (NN*DD + 2*NN*TOPK) * 4;                   // 212992 bytes
    const int TOPK_SMEM = (64*TP + ROWS_PER_BLK*NN + NN) * 4;        // 149760 bytes
    const int GEMM_SMEM = (2*128*AP + 2*64*AP) * 4;                  // 104448 bytes

    static cudaStream_t s2 = nullptr;
    static cudaEvent_t evFork = nullptr, evJoin = nullptr;
    if (!s2) {
        cudaFuncSetAttribute(k_aggr, cudaFuncAttributeMaxDynamicSharedMemorySize, AGG_SMEM);
        cudaFuncSetAttribute(k_topk, cudaFuncAttributeMaxDynamicSharedMemorySize, TOPK_SMEM);
        cudaFuncSetAttribute(k_gemm, cudaFuncAttributeMaxDynamicSharedMemorySize, GEMM_SMEM);
        cudaStreamCreateWithFlags(&s2, cudaStreamNonBlocking);
        cudaEventCreateWithFlags(&evFork, cudaEventDisableTiming);
        cudaEventCreateWithFlags(&evJoin, cudaEventDisableTiming);
    }

    // fork: k_topk on s2 runs concurrently with k_gemm on the main stream
    cudaEventRecord(evFork, 0);
    cudaStreamWaitEvent(s2, evFork, 0);
    k_topk <<<NN/ROWS_PER_BLK, 512, TOPK_SMEM, s2>>>(emb, attn_w);
    cudaEventRecord(evJoin, s2);

    k_gemm <<<M_ROWS/128, 256, GEMM_SMEM>>>(data, fc_w, fc_b, attn_w);

    // join: k_aggr needs g_topk/g_tsrc/g_tdst (topk) and g_z/g_ssrc/g_sdst (gemm)
    cudaStreamWaitEvent(0, evJoin, 0);
    k_aggr <<<BB, 512, AGG_SMEM>>>(emb, attn_b, bn_gamma, bn_beta, out_w, out_b, out);
}